// round 4
// baseline (speedup 1.0000x reference)
#include <cuda_runtime.h>
#include <cuda_fp16.h>

#define RES    512
#define NCOMP  64
#define NPTS_MAX 1048576
#define NBIN   32768          // 32^3

// Channel-last fp16 scratch: [plane][y][x][c]  = 100.5 MB (< L2)
__device__ __half g_planeT[3ull * RES * RES * NCOMP];
// Binning scratch
__device__ unsigned g_binCnt[NBIN];
__device__ unsigned g_binCursor[NBIN];
__device__ float4   g_sorted[NPTS_MAX];   // (x, y, z, orig_idx_as_bits)

// ---------------------------------------------------------------------------
// Transpose+convert (C,R,R) fp32 -> (R,R,C) fp16 per plane.
// ---------------------------------------------------------------------------
__global__ void tp_kernel(const float* __restrict__ in) {
    __shared__ float tile[NCOMP][33];
    const int tx = threadIdx.x;
    const int ty = threadIdx.y;
    const int x0 = blockIdx.x * 32;
    const int y  = blockIdx.y;
    const int p  = blockIdx.z;

    const float* src = in + ((size_t)(p * NCOMP) * RES + y) * RES + x0;
#pragma unroll
    for (int j = 0; j < 8; j++) {
        const int c = ty + j * 8;
        tile[c][tx] = src[(size_t)c * RES * RES + tx];
    }
    __syncthreads();

    half2* dst = (half2*)g_planeT
               + ((size_t)p * RES * RES + (size_t)y * RES + x0) * (NCOMP / 2);
#pragma unroll
    for (int j = 0; j < 4; j++) {
        const int xl = ty + j * 8;
        dst[(size_t)xl * (NCOMP / 2) + tx] =
            __floats2half2_rn(tile[2 * tx][xl], tile[2 * tx + 1][xl]);
    }
}

// ---------------------------------------------------------------------------
// Binning: Morton-ordered 32^3 counting sort.
// ---------------------------------------------------------------------------
__device__ __forceinline__ unsigned spread3(unsigned v) {  // 5 bits -> every 3rd bit
    v &= 0x3FF;
    v = (v | (v << 16)) & 0x030000FF;
    v = (v | (v << 8))  & 0x0300F00F;
    v = (v | (v << 4))  & 0x030C30C3;
    v = (v | (v << 2))  & 0x09249249;
    return v;
}

__device__ __forceinline__ unsigned point_bin(float x, float y, float z) {
    const unsigned bx = (unsigned)min(31, max(0, (int)((x + 1.0f) * 16.0f)));
    const unsigned by = (unsigned)min(31, max(0, (int)((y + 1.0f) * 16.0f)));
    const unsigned bz = (unsigned)min(31, max(0, (int)((z + 1.0f) * 16.0f)));
    return spread3(bx) | (spread3(by) << 1) | (spread3(bz) << 2);
}

__global__ void zero_kernel() {
    const int i = blockIdx.x * blockDim.x + threadIdx.x;
    if (i < NBIN) g_binCnt[i] = 0;
}

__global__ void hist_kernel(const float* __restrict__ pts, int n_pts) {
    const int i = blockIdx.x * blockDim.x + threadIdx.x;
    if (i >= n_pts) return;
    const float x = pts[3 * (size_t)i + 0];
    const float y = pts[3 * (size_t)i + 1];
    const float z = pts[3 * (size_t)i + 2];
    atomicAdd(&g_binCnt[point_bin(x, y, z)], 1u);
}

__global__ void scan_kernel() {   // single block, 1024 threads, 32 bins each
    __shared__ unsigned part[1024];
    const int t = threadIdx.x;
    const unsigned base = (unsigned)t * 32u;
    unsigned s = 0;
#pragma unroll
    for (int i = 0; i < 32; i++) s += g_binCnt[base + i];
    part[t] = s;
    __syncthreads();
    for (int d = 1; d < 1024; d <<= 1) {
        const unsigned v = (t >= d) ? part[t - d] : 0u;
        __syncthreads();
        part[t] += v;
        __syncthreads();
    }
    unsigned run = (t == 0) ? 0u : part[t - 1];
#pragma unroll
    for (int i = 0; i < 32; i++) {
        const unsigned c = g_binCnt[base + i];
        g_binCursor[base + i] = run;
        run += c;
    }
}

__global__ void scatter_kernel(const float* __restrict__ pts, int n_pts) {
    const int i = blockIdx.x * blockDim.x + threadIdx.x;
    if (i >= n_pts) return;
    const float x = pts[3 * (size_t)i + 0];
    const float y = pts[3 * (size_t)i + 1];
    const float z = pts[3 * (size_t)i + 2];
    const unsigned slot = atomicAdd(&g_binCursor[point_bin(x, y, z)], 1u);
    g_sorted[slot] = make_float4(x, y, z, __int_as_float(i));
}

// ---------------------------------------------------------------------------
// Gather: 8 lanes per point, lane owns 8 channels (one LDG.128 per corner).
// Points consumed in Morton-bin order -> plane gathers hit L1/L2.
// ---------------------------------------------------------------------------
__device__ __forceinline__ void acc8(float* a, const uint4 v, const float w) {
    const float2 f0 = __half22float2(*(const half2*)&v.x);
    const float2 f1 = __half22float2(*(const half2*)&v.y);
    const float2 f2 = __half22float2(*(const half2*)&v.z);
    const float2 f3 = __half22float2(*(const half2*)&v.w);
    a[0] = fmaf(f0.x, w, a[0]);  a[1] = fmaf(f0.y, w, a[1]);
    a[2] = fmaf(f1.x, w, a[2]);  a[3] = fmaf(f1.y, w, a[3]);
    a[4] = fmaf(f2.x, w, a[4]);  a[5] = fmaf(f2.y, w, a[5]);
    a[6] = fmaf(f3.x, w, a[6]);  a[7] = fmaf(f3.y, w, a[7]);
}

__global__ void sample_kernel(float4* __restrict__ out, int n_pts) {
    const int tid = (int)(blockIdx.x * blockDim.x + threadIdx.x);
    const int pt  = tid >> 3;
    if (pt >= n_pts) return;
    const unsigned sub = (unsigned)(tid & 7);

    const float4 pv = __ldg(&g_sorted[pt]);
    const int oidx  = __float_as_int(pv.w);

    // plane 0: (x=p0, y=p1); plane 1: (x=p0, y=p2); plane 2: (x=p1, y=p2)
    const float us[3] = {pv.x, pv.x, pv.y};
    const float vs[3] = {pv.y, pv.z, pv.z};
    const float rm1 = (float)(RES - 1);

    float acc[8] = {0.f, 0.f, 0.f, 0.f, 0.f, 0.f, 0.f, 0.f};
    const char* __restrict__ base = (const char*)g_planeT;
    const unsigned laneoff = sub << 4;

#pragma unroll
    for (int p = 0; p < 3; p++) {
        float fx = fminf(fmaxf((us[p] + 1.0f) * 0.5f * rm1, 0.0f), rm1);
        float fy = fminf(fmaxf((vs[p] + 1.0f) * 0.5f * rm1, 0.0f), rm1);
        const float x0f = floorf(fx);
        const float y0f = floorf(fy);
        const float wx = fx - x0f;
        const float wy = fy - y0f;
        const int x0 = (int)x0f;
        const int y0 = (int)y0f;
        const int x1 = min(x0 + 1, RES - 1);
        const int y1 = min(y0 + 1, RES - 1);

        const unsigned r0 = (unsigned)((p * RES + y0) * RES);
        const unsigned r1 = (unsigned)((p * RES + y1) * RES);
        const unsigned o00 = ((r0 + (unsigned)x0) << 7) + laneoff;
        const unsigned o01 = ((r0 + (unsigned)x1) << 7) + laneoff;
        const unsigned o10 = ((r1 + (unsigned)x0) << 7) + laneoff;
        const unsigned o11 = ((r1 + (unsigned)x1) << 7) + laneoff;

        const uint4 v00 = __ldg((const uint4*)(base + o00));
        const uint4 v01 = __ldg((const uint4*)(base + o01));
        const uint4 v10 = __ldg((const uint4*)(base + o10));
        const uint4 v11 = __ldg((const uint4*)(base + o11));

        const float w00 = (1.0f - wx) * (1.0f - wy);
        const float w01 = wx * (1.0f - wy);
        const float w10 = (1.0f - wx) * wy;
        const float w11 = wx * wy;

        acc8(acc, v00, w00);
        acc8(acc, v01, w01);
        acc8(acc, v10, w10);
        acc8(acc, v11, w11);
    }

    float4* orow = out + (size_t)oidx * 16 + sub * 2;
    __stcs(orow,     make_float4(acc[0], acc[1], acc[2], acc[3]));
    __stcs(orow + 1, make_float4(acc[4], acc[5], acc[6], acc[7]));
}

extern "C" void kernel_launch(void* const* d_in, const int* in_sizes, int n_in,
                              void* d_out, int out_size) {
    const float* in_tensor  = (const float*)d_in[0];   // (N, 3) fp32
    const float* plane_coef = (const float*)d_in[1];   // (3, 64, 512, 512) fp32
    float4* out = (float4*)d_out;                      // (N, 64) fp32

    const int n_pts = in_sizes[0] / 3;
    const int nb256 = (n_pts + 255) / 256;

    // 1) plane reorder + fp16 convert
    dim3 tgrid(RES / 32, RES, 3);
    tp_kernel<<<tgrid, dim3(32, 8)>>>(plane_coef);

    // 2) Morton counting sort of points
    zero_kernel<<<(NBIN + 255) / 256, 256>>>();
    hist_kernel<<<nb256, 256>>>(in_tensor, n_pts);
    scan_kernel<<<1, 1024>>>();
    scatter_kernel<<<nb256, 256>>>(in_tensor, n_pts);

    // 3) gather in bin order: 8 lanes per point
    const int pts_per_blk = 256 / 8;
    const int nblk = (n_pts + pts_per_blk - 1) / pts_per_blk;
    sample_kernel<<<nblk, 256>>>(out, n_pts);
}

// round 7
// speedup vs baseline: 1.7794x; 1.7794x over previous
#include <cuda_runtime.h>
#include <cuda_fp16.h>

#define RES    512
#define NCOMP  64

// Channel-last fp16 scratch: [plane][y][x][c]  = 3*512*512*64*2B = 100.5 MB (< 126MB L2)
__device__ __half g_planeT[3ull * RES * RES * NCOMP];

// ---------------- 256-bit L2 eviction-priority accessors -------------------
// sm_103a ptxas only accepts L2::evict_* on .v8.b32 forms.
__device__ __forceinline__ void ldg_256_el(const void* p, unsigned* v) {
    asm("ld.global.nc.L2::evict_last.v8.b32 {%0,%1,%2,%3,%4,%5,%6,%7}, [%8];"
        : "=r"(v[0]), "=r"(v[1]), "=r"(v[2]), "=r"(v[3]),
          "=r"(v[4]), "=r"(v[5]), "=r"(v[6]), "=r"(v[7])
        : "l"(p));
}
__device__ __forceinline__ void stg_256_el(void* p, const unsigned* v) {
    asm volatile("st.global.L2::evict_last.v8.b32 [%0], {%1,%2,%3,%4,%5,%6,%7,%8};"
                 :: "l"(p), "r"(v[0]), "r"(v[1]), "r"(v[2]), "r"(v[3]),
                    "r"(v[4]), "r"(v[5]), "r"(v[6]), "r"(v[7]) : "memory");
}
__device__ __forceinline__ void stg_256_ef(void* p, const float* f) {
    asm volatile("st.global.L2::evict_first.v8.b32 [%0], {%1,%2,%3,%4,%5,%6,%7,%8};"
                 :: "l"(p),
                    "r"(__float_as_uint(f[0])), "r"(__float_as_uint(f[1])),
                    "r"(__float_as_uint(f[2])), "r"(__float_as_uint(f[3])),
                    "r"(__float_as_uint(f[4])), "r"(__float_as_uint(f[5])),
                    "r"(__float_as_uint(f[6])), "r"(__float_as_uint(f[7])) : "memory");
}

// ---------------------------------------------------------------------------
// Transpose+convert (C,R,R) fp32 -> (R,R,C) fp16 per plane.
// Plane scratch written with evict_last 256-bit stores -> enters L2 warm.
// grid: (RES/32, RES, 3), block (32, 8).
// ---------------------------------------------------------------------------
__global__ void tp_kernel(const float* __restrict__ in) {
    __shared__ float tile[NCOMP][33];
    const int tx = threadIdx.x;
    const int ty = threadIdx.y;
    const int x0 = blockIdx.x * 32;
    const int y  = blockIdx.y;
    const int p  = blockIdx.z;

    const float* src = in + ((size_t)(p * NCOMP) * RES + y) * RES + x0;
#pragma unroll
    for (int j = 0; j < 8; j++) {
        const int c = ty + j * 8;                          // channel 0..63
        tile[c][tx] = __ldg(src + (size_t)c * RES * RES + tx);
    }
    __syncthreads();

    // Store phase: 128 work items = 32 x-locals * 4 chunks of 16 channels (32B)
    const int t = ty * 32 + tx;
    if (t < 128) {
        const int xl = t >> 2;                             // x-local 0..31
        const int ch = (t & 3) * 16;                       // chunk start channel
        unsigned v[8];
#pragma unroll
        for (int k = 0; k < 8; k++) {
            const half2 h = __floats2half2_rn(tile[ch + 2 * k][xl],
                                              tile[ch + 2 * k + 1][xl]);
            v[k] = *(const unsigned*)&h;
        }
        __half* dst = g_planeT
            + ((size_t)p * RES * RES + (size_t)y * RES + (x0 + xl)) * NCOMP + ch;
        stg_256_el(dst, v);
    }
}

// ---------------------------------------------------------------------------
// Gather: 4 lanes per point, lane owns 16 channels (one 32B evict_last load
// per corner; 4 lanes cover exactly one 128B texel line).
// ---------------------------------------------------------------------------
__device__ __forceinline__ void acc16(float* a, const unsigned* v, const float w) {
#pragma unroll
    for (int k = 0; k < 8; k++) {
        const float2 f = __half22float2(*(const half2*)&v[k]);
        a[2 * k]     = fmaf(f.x, w, a[2 * k]);
        a[2 * k + 1] = fmaf(f.y, w, a[2 * k + 1]);
    }
}

__global__ void sample_kernel(const float* __restrict__ pts,
                              float* __restrict__ out,
                              int n_pts) {
    const int tid = (int)(blockIdx.x * blockDim.x + threadIdx.x);
    const int pt  = tid >> 2;
    if (pt >= n_pts) return;
    const unsigned sub = (unsigned)(tid & 3);      // channels [16*sub, 16*sub+16)

    const float px = __ldg(pts + 3 * (size_t)pt + 0);
    const float py = __ldg(pts + 3 * (size_t)pt + 1);
    const float pz = __ldg(pts + 3 * (size_t)pt + 2);

    // plane 0: (x=p0, y=p1); plane 1: (x=p0, y=p2); plane 2: (x=p1, y=p2)
    const float us[3] = {px, px, py};
    const float vs[3] = {py, pz, pz};
    const float rm1 = (float)(RES - 1);

    float acc[16];
#pragma unroll
    for (int k = 0; k < 16; k++) acc[k] = 0.0f;

    const char* __restrict__ base = (const char*)g_planeT;
    const unsigned laneoff = sub << 5;             // 32B per lane within 128B texel

#pragma unroll
    for (int p = 0; p < 3; p++) {
        float fx = fminf(fmaxf((us[p] + 1.0f) * 0.5f * rm1, 0.0f), rm1);
        float fy = fminf(fmaxf((vs[p] + 1.0f) * 0.5f * rm1, 0.0f), rm1);
        const float x0f = floorf(fx);
        const float y0f = floorf(fy);
        const float wx = fx - x0f;
        const float wy = fy - y0f;
        const int x0 = (int)x0f;
        const int y0 = (int)y0f;
        const int x1 = min(x0 + 1, RES - 1);
        const int y1 = min(y0 + 1, RES - 1);

        // texel byte offset = ((p*RES + y)*RES + x) * 128  (max ~100.6MB -> u32)
        const unsigned r0 = (unsigned)((p * RES + y0) * RES);
        const unsigned r1 = (unsigned)((p * RES + y1) * RES);
        const unsigned o00 = ((r0 + (unsigned)x0) << 7) + laneoff;
        const unsigned o01 = ((r0 + (unsigned)x1) << 7) + laneoff;
        const unsigned o10 = ((r1 + (unsigned)x0) << 7) + laneoff;
        const unsigned o11 = ((r1 + (unsigned)x1) << 7) + laneoff;

        unsigned v00[8], v01[8], v10[8], v11[8];
        ldg_256_el(base + o00, v00);
        ldg_256_el(base + o01, v01);
        ldg_256_el(base + o10, v10);
        ldg_256_el(base + o11, v11);

        const float w00 = (1.0f - wx) * (1.0f - wy);
        const float w01 = wx * (1.0f - wy);
        const float w10 = (1.0f - wx) * wy;
        const float w11 = wx * wy;

        acc16(acc, v00, w00);
        acc16(acc, v01, w01);
        acc16(acc, v10, w10);
        acc16(acc, v11, w11);
    }

    // out row = 64 floats = 256B; lane owns 64B = 2 x 32B evict_first stores
    float* orow = out + (size_t)pt * NCOMP + sub * 16;
    stg_256_ef(orow,     acc);
    stg_256_ef(orow + 8, acc + 8);
}

extern "C" void kernel_launch(void* const* d_in, const int* in_sizes, int n_in,
                              void* d_out, int out_size) {
    const float* in_tensor  = (const float*)d_in[0];   // (N, 3) fp32
    const float* plane_coef = (const float*)d_in[1];   // (3, 64, 512, 512) fp32
    float* out = (float*)d_out;                        // (N, 64) fp32

    const int n_pts = in_sizes[0] / 3;

    // 1) reorder + fp16-convert planes; result left hot in L2 (evict_last)
    dim3 tgrid(RES / 32, RES, 3);
    tp_kernel<<<tgrid, dim3(32, 8)>>>(plane_coef);

    // 2) gather: 4 lanes per point, 64 points per 256-thread block
    const int pts_per_blk = 256 / 4;
    const int nblk = (n_pts + pts_per_blk - 1) / pts_per_blk;
    sample_kernel<<<nblk, 256>>>(in_tensor, out, n_pts);
}